// round 6
// baseline (speedup 1.0000x reference)
#include <cuda_runtime.h>

// ---------------------------------------------------------------------------
// GraphConstruction: A[i,j] = all_k( ||patch_i[:,k]-patch_j[:,k]||_2 <= 7 )
// score_k(i,j) = sum_{r<16} P[i,r,k]*P[j,r,k] + 1*c_j + c_i*1,  c = 12.25-sq/2
// A[i,j] = no k has score_k < 0 (OR of sign bits == 0).
// FFMA2 chain order/operands identical to R2/R3 (rel_err bit-stable).
// R5: broadcast MOVs removed via smem-duplicated A operands (LDS.128 dup pairs).
// ---------------------------------------------------------------------------

#define NP 4096
#define RAUG 18

static __device__ float g_P[16 * RAUG * NP];   // [k][r][n], 4.5 MB

// ---------------- helpers ---------------------------------------------------
__device__ __forceinline__ void ffma2(unsigned long long& d,
                                      unsigned long long a,
                                      unsigned long long b) {
    asm("fma.rn.f32x2 %0, %1, %2, %3;" : "=l"(d) : "l"(a), "l"(b), "l"(d));
}
__device__ __forceinline__ void split2(unsigned& lo, unsigned& hi,
                                       unsigned long long v) {
    asm("mov.b64 {%0, %1}, %2;" : "=r"(lo), "=r"(hi) : "l"(v));
}
__device__ __forceinline__ unsigned prmt(unsigned a, unsigned b, unsigned sel) {
    unsigned d;
    asm("prmt.b32 %0, %1, %2, %3;" : "=r"(d) : "r"(a), "r"(b), "r"(sel));
    return d;
}
__device__ __forceinline__ void cp_async16(void* smem, const void* gmem) {
    unsigned s = (unsigned)__cvta_generic_to_shared(smem);
    asm volatile("cp.async.cg.shared.global [%0], [%1], 16;" :: "r"(s), "l"(gmem));
}
#define CP_COMMIT() asm volatile("cp.async.commit_group;")
#define CP_WAIT0()  asm volatile("cp.async.wait_group 0;")

// ---------------- prep 1: gather x into g_P rows 0..15 ----------------------
// One block per (r,k) slice: coalesced 64B row-segment reads, contiguous writes.
__global__ void prep1_kernel(const float* __restrict__ x) {
    const int k = blockIdx.x & 15;
    const int r = blockIdx.x >> 4;
    const int t = threadIdx.x;                 // 256 threads
    const int w = ((16 * (r & 3) + k) << 4) + (t & 15);
    const int hbase = ((r >> 2) << 4) + (t >> 4);
    float v[16];
#pragma unroll
    for (int c = 0; c < 16; c++) {
        int h = (c << 6) + hbase;              // n = t*16 + c decomposition
        v[c] = x[h * 1024 + w];
    }
    float* dst = &g_P[(k * RAUG + r) * NP + t * 16];
#pragma unroll
    for (int q = 0; q < 4; q++)
        *(float4*)(dst + q * 4) =
            make_float4(v[q * 4], v[q * 4 + 1], v[q * 4 + 2], v[q * 4 + 3]);
}

// ---------------- prep 2: augmentation rows 16,17 ---------------------------
__global__ void prep2_kernel() {
    int idx = blockIdx.x * blockDim.x + threadIdx.x;   // [0, 16*1024)
    int n4 = idx & 1023;
    int k = idx >> 10;
    float s[4] = {0.0f, 0.0f, 0.0f, 0.0f};
#pragma unroll
    for (int r = 0; r < 16; r++) {
        float4 v = *(const float4*)&g_P[(k * RAUG + r) * NP + n4 * 4];
        s[0] = fmaf(v.x, v.x, s[0]);
        s[1] = fmaf(v.y, v.y, s[1]);
        s[2] = fmaf(v.z, v.z, s[2]);
        s[3] = fmaf(v.w, v.w, s[3]);
    }
    *(float4*)&g_P[(k * RAUG + 16) * NP + n4 * 4] =
        make_float4(1.0f, 1.0f, 1.0f, 1.0f);
    *(float4*)&g_P[(k * RAUG + 17) * NP + n4 * 4] =
        make_float4(12.25f - 0.5f * s[0], 12.25f - 0.5f * s[1],
                    12.25f - 0.5f * s[2], 12.25f - 0.5f * s[3]);
}

// ---------------- main: tiled pair kernel -----------------------------------
// Tile 64 i x 128 j, 128 threads, 8x8 per thread (j packed as f32x2).
// A operands pre-duplicated into sAd each k: zero broadcast MOVs in hot loop.
__global__ void __launch_bounds__(128, 4) gram_kernel(float* __restrict__ A) {
    const int bid = blockIdx.x;
    int jb = (int)(0.5f * (sqrtf(4.0f * (float)bid + 1.0f) - 1.0f));
    while (jb * (jb + 1) > bid) jb--;
    while ((jb + 1) * (jb + 2) <= bid) jb++;
    const int ib = bid - jb * (jb + 1);        // 0 .. 2*jb+1

    __shared__ __align__(16) float sAc[RAUG][64];        // compact A (cp.async dst)
    __shared__ __align__(16) float sAd[RAUG][128];       // duplicated A pairs
    __shared__ __align__(16) float sB[2][RAUG][128];     // B double buffer

    const int tid = threadIdx.x;
    const int tx = tid & 15;             // j group: j = {tx*4..+3} U {64+tx*4..+3}
    const int ty = tid >> 4;             // i group 0..7
    const int i0 = ib * 64;
    const int j0 = jb * 128;

    auto issueA = [&](int k) {
#pragma unroll
        for (int idx = tid; idx < 288; idx += 128) {     // 18 x 16 float4
            int r = idx >> 4, c = idx & 15;
            cp_async16(&sAc[r][c * 4], &g_P[(k * RAUG + r) * NP + i0 + c * 4]);
        }
    };
    auto issueB = [&](int buf, int k) {
#pragma unroll
        for (int idx = tid; idx < 576; idx += 128) {     // 18 x 32 float4
            int r = idx >> 5, c = idx & 31;
            int rs = (r < 16) ? r : (33 - r);            // rows 16/17 swapped
            cp_async16(&sB[buf][r][c * 4], &g_P[(k * RAUG + rs) * NP + j0 + c * 4]);
        }
    };

    unsigned msk[8][2];
#pragma unroll
    for (int a = 0; a < 8; a++) { msk[a][0] = 0u; msk[a][1] = 0u; }

    issueA(0);
    issueB(0, 0);
    CP_COMMIT();

#pragma unroll 1
    for (int k = 0; k < 16; k++) {
        const int buf = k & 1;
        CP_WAIT0();
        __syncthreads();          // sAc/sB[buf] staged; compute(k-1) fully done

        // duplicate A slice: sAd[r][2i],[2i+1] = sAc[r][i]  (1152 values, 9/thr)
#pragma unroll
        for (int q = 0; q < 9; q++) {
            int idx = tid + q * 128;
            int r = idx >> 6, i = idx & 63;
            float v = sAc[r][i];
            *(float2*)&sAd[r][2 * i] = make_float2(v, v);
        }
        __syncthreads();          // sAd ready; sAc free for next prefetch

        if (k < 15) {
            issueA(k + 1);
            issueB(buf ^ 1, k + 1);
            CP_COMMIT();
        }

        unsigned long long acc[8][4];
#pragma unroll
        for (int a = 0; a < 8; a++)
#pragma unroll
            for (int b = 0; b < 4; b++) acc[a][b] = 0ULL;

#pragma unroll
        for (int r = 0; r < RAUG; r++) {
            ulonglong2 a01 = *(const ulonglong2*)&sAd[r][ty * 16];
            ulonglong2 a23 = *(const ulonglong2*)&sAd[r][ty * 16 + 4];
            ulonglong2 a45 = *(const ulonglong2*)&sAd[r][ty * 16 + 8];
            ulonglong2 a67 = *(const ulonglong2*)&sAd[r][ty * 16 + 12];
            ulonglong2 b0 = *(const ulonglong2*)&sB[buf][r][tx * 4];
            ulonglong2 b1 = *(const ulonglong2*)&sB[buf][r][64 + tx * 4];
            unsigned long long aa[8] = {a01.x, a01.y, a23.x, a23.y,
                                        a45.x, a45.y, a67.x, a67.y};
            unsigned long long bb[4] = {b0.x, b0.y, b1.x, b1.y};
#pragma unroll
            for (int ii = 0; ii < 8; ii++)
#pragma unroll
                for (int jj = 0; jj < 4; jj++) ffma2(acc[ii][jj], aa[ii], bb[jj]);
        }

        // fold sign bits: msk[ii][p] bytes = signs of j = p*64 + tx*4 + {0..3}
#pragma unroll
        for (int ii = 0; ii < 8; ii++)
#pragma unroll
            for (int p = 0; p < 2; p++) {
                unsigned lo0, hi0, lo1, hi1;
                split2(lo0, hi0, acc[ii][2 * p]);
                split2(lo1, hi1, acc[ii][2 * p + 1]);
                unsigned t0 = prmt(lo0, hi0, 0xFBFBu);
                unsigned t1 = prmt(lo1, hi1, 0xFBFBu);
                msk[ii][p] |= prmt(t0, t1, 0x5410u);
            }
    }

    // ---- epilogue: sign byte==0 -> 1.0f ----
    // direct: A[i, j]
#pragma unroll
    for (int ii = 0; ii < 8; ii++)
#pragma unroll
        for (int p = 0; p < 2; p++) {
            unsigned m = msk[ii][p];
            float4 o;
            o.x = (m & 0x00000080u) ? 0.0f : 1.0f;
            o.y = (m & 0x00008000u) ? 0.0f : 1.0f;
            o.z = (m & 0x00800000u) ? 0.0f : 1.0f;
            o.w = (m & 0x80000000u) ? 0.0f : 1.0f;
            size_t off = (size_t)(i0 + ty * 8 + ii) * 4096 + j0 + p * 64 + tx * 4;
            *(float4*)&A[off] = o;
        }
    // transposed: A[j, i]; skip rows inside this tile's i-range (diag tiles)
#pragma unroll
    for (int p = 0; p < 2; p++)
#pragma unroll
        for (int c = 0; c < 4; c++) {
            int rowj = j0 + p * 64 + tx * 4 + c;
            if (rowj >= i0 && rowj < i0 + 64) continue;   // covered by direct side
            unsigned bit = 0x80u << (8 * c);
            float4 o0, o1;
            o0.x = (msk[0][p] & bit) ? 0.0f : 1.0f;
            o0.y = (msk[1][p] & bit) ? 0.0f : 1.0f;
            o0.z = (msk[2][p] & bit) ? 0.0f : 1.0f;
            o0.w = (msk[3][p] & bit) ? 0.0f : 1.0f;
            o1.x = (msk[4][p] & bit) ? 0.0f : 1.0f;
            o1.y = (msk[5][p] & bit) ? 0.0f : 1.0f;
            o1.z = (msk[6][p] & bit) ? 0.0f : 1.0f;
            o1.w = (msk[7][p] & bit) ? 0.0f : 1.0f;
            size_t off = (size_t)rowj * 4096 + i0 + ty * 8;
            *(float4*)&A[off]     = o0;
            *(float4*)&A[off + 4] = o1;
        }
}

// ---------------------------------------------------------------------------
extern "C" void kernel_launch(void* const* d_in, const int* in_sizes, int n_in,
                              void* d_out, int out_size) {
    const float* x = (const float*)d_in[0];
    float* A = (float*)d_out;

    prep1_kernel<<<256, 256>>>(x);         // one block per (r,k) slice
    prep2_kernel<<<64, 256>>>();           // rows 16,17
    gram_kernel<<<1056, 128>>>(A);         // 64x128 triangle tiles
}

// round 7
// speedup vs baseline: 1.2600x; 1.2600x over previous
#include <cuda_runtime.h>

// ---------------------------------------------------------------------------
// GraphConstruction: A[i,j] = all_k( ||patch_i[:,k]-patch_j[:,k]||_2 <= 7 )
// score_k(i,j) = sum_{r<16} P[i,r,k]*P[j,r,k] + 1*c_j + c_i*1,  c = 12.25-sq/2
// A[i,j] = no k has score_k < 0 (OR of sign bits == 0).
// Inner loop identical to R2/R3 (bit-stable rel_err); tiles 64x64 for finer
// per-SM work quantization (147K -> 138K cyc makespan).
// ---------------------------------------------------------------------------

#define NP 4096
#define RAUG 18

static __device__ float g_P[16 * RAUG * NP];   // [k][r][n], 4.5 MB

// ---------------- helpers ---------------------------------------------------
__device__ __forceinline__ unsigned long long bcast2(float x) {
    unsigned long long r;
    asm("mov.b64 %0, {%1, %1};" : "=l"(r) : "f"(x));
    return r;
}
__device__ __forceinline__ void ffma2(unsigned long long& d,
                                      unsigned long long a,
                                      unsigned long long b) {
    asm("fma.rn.f32x2 %0, %1, %2, %3;" : "=l"(d) : "l"(a), "l"(b), "l"(d));
}
__device__ __forceinline__ void split2(unsigned& lo, unsigned& hi,
                                       unsigned long long v) {
    asm("mov.b64 {%0, %1}, %2;" : "=r"(lo), "=r"(hi) : "l"(v));
}
__device__ __forceinline__ unsigned prmt(unsigned a, unsigned b, unsigned sel) {
    unsigned d;
    asm("prmt.b32 %0, %1, %2, %3;" : "=r"(d) : "r"(a), "r"(b), "r"(sel));
    return d;
}
__device__ __forceinline__ void cp_async16(void* smem, const void* gmem) {
    unsigned s = (unsigned)__cvta_generic_to_shared(smem);
    asm volatile("cp.async.cg.shared.global [%0], [%1], 16;" :: "r"(s), "l"(gmem));
}
#define CP_COMMIT() asm volatile("cp.async.commit_group;")
#define CP_WAIT0()  asm volatile("cp.async.wait_group 0;")

// ---------------- prep 1: gather x into g_P rows 0..15 ----------------------
__global__ void prep1_kernel(const float* __restrict__ x) {
    const int k = blockIdx.x & 15;
    const int r = blockIdx.x >> 4;
    const int t = threadIdx.x;                 // 256 threads
    const int w = ((16 * (r & 3) + k) << 4) + (t & 15);
    const int hbase = ((r >> 2) << 4) + (t >> 4);
    float v[16];
#pragma unroll
    for (int c = 0; c < 16; c++) {
        int h = (c << 6) + hbase;              // n = t*16 + c decomposition
        v[c] = x[h * 1024 + w];
    }
    float* dst = &g_P[(k * RAUG + r) * NP + t * 16];
#pragma unroll
    for (int q = 0; q < 4; q++)
        *(float4*)(dst + q * 4) =
            make_float4(v[q * 4], v[q * 4 + 1], v[q * 4 + 2], v[q * 4 + 3]);
}

// ---------------- prep 2: augmentation rows 16,17 ---------------------------
__global__ void prep2_kernel() {
    int idx = blockIdx.x * blockDim.x + threadIdx.x;   // [0, 16*1024)
    int n4 = idx & 1023;
    int k = idx >> 10;
    float s[4] = {0.0f, 0.0f, 0.0f, 0.0f};
#pragma unroll
    for (int r = 0; r < 16; r++) {
        float4 v = *(const float4*)&g_P[(k * RAUG + r) * NP + n4 * 4];
        s[0] = fmaf(v.x, v.x, s[0]);
        s[1] = fmaf(v.y, v.y, s[1]);
        s[2] = fmaf(v.z, v.z, s[2]);
        s[3] = fmaf(v.w, v.w, s[3]);
    }
    *(float4*)&g_P[(k * RAUG + 16) * NP + n4 * 4] =
        make_float4(1.0f, 1.0f, 1.0f, 1.0f);
    *(float4*)&g_P[(k * RAUG + 17) * NP + n4 * 4] =
        make_float4(12.25f - 0.5f * s[0], 12.25f - 0.5f * s[1],
                    12.25f - 0.5f * s[2], 12.25f - 0.5f * s[3]);
}

// ---------------- main: tiled pair kernel -----------------------------------
// Tile 64 i x 64 j, 64 threads, 8x8 per thread (j packed as f32x2).
// Triangle grid of 2080 tiles (ib <= jb). Inner loop identical to R2/R3.
__global__ void __launch_bounds__(64, 8) gram_kernel(float* __restrict__ A) {
    const int bid = blockIdx.x;
    int jb = (int)((sqrtf(8.0f * (float)bid + 1.0f) - 1.0f) * 0.5f);
    while ((jb * (jb + 1)) / 2 > bid) jb--;
    while (((jb + 1) * (jb + 2)) / 2 <= bid) jb++;
    const int ib = bid - (jb * (jb + 1)) / 2;   // 0..jb
    const int i0 = ib * 64;
    const int j0 = jb * 64;

    __shared__ __align__(16) float sA[2][RAUG][64];
    __shared__ __align__(16) float sB[2][RAUG][64];

    const int tid = threadIdx.x;
    const int tx = tid & 7;              // j group: j = {tx*4..+3} U {32+tx*4..+3}
    const int ty = tid >> 3;             // i group 0..7

    auto issue = [&](int buf, int k) {
        for (int idx = tid; idx < 288; idx += 64) {      // sA: 18 x 16 float4
            int r = idx >> 4, c = idx & 15;
            cp_async16(&sA[buf][r][c * 4], &g_P[(k * RAUG + r) * NP + i0 + c * 4]);
        }
        for (int idx = tid; idx < 288; idx += 64) {      // sB: rows 16/17 swapped
            int r = idx >> 4, c = idx & 15;
            int rs = (r < 16) ? r : (33 - r);
            cp_async16(&sB[buf][r][c * 4], &g_P[(k * RAUG + rs) * NP + j0 + c * 4]);
        }
    };

    unsigned msk[8][2];
#pragma unroll
    for (int a = 0; a < 8; a++) { msk[a][0] = 0u; msk[a][1] = 0u; }

    issue(0, 0);
    CP_COMMIT();

#pragma unroll 1
    for (int k = 0; k < 16; k++) {
        const int buf = k & 1;
        CP_WAIT0();
        __syncthreads();          // buf staged AND everyone done with buf^1
        if (k < 15) {
            issue(buf ^ 1, k + 1);
            CP_COMMIT();
        }

        unsigned long long acc[8][4];
#pragma unroll
        for (int a = 0; a < 8; a++)
#pragma unroll
            for (int b = 0; b < 4; b++) acc[a][b] = 0ULL;

#pragma unroll
        for (int r = 0; r < RAUG; r++) {
            float4 a0 = *(const float4*)&sA[buf][r][ty * 8];
            float4 a1 = *(const float4*)&sA[buf][r][ty * 8 + 4];
            ulonglong2 b0 = *(const ulonglong2*)&sB[buf][r][tx * 4];
            ulonglong2 b1 = *(const ulonglong2*)&sB[buf][r][32 + tx * 4];
            unsigned long long bb[4] = {b0.x, b0.y, b1.x, b1.y};
            float av[8] = {a0.x, a0.y, a0.z, a0.w, a1.x, a1.y, a1.z, a1.w};
#pragma unroll
            for (int ii = 0; ii < 8; ii++) {
                unsigned long long aa = bcast2(av[ii]);
#pragma unroll
                for (int jj = 0; jj < 4; jj++) ffma2(acc[ii][jj], aa, bb[jj]);
            }
        }

        // fold sign bits: msk[ii][p] bytes = signs of j = p*32 + tx*4 + {0..3}
#pragma unroll
        for (int ii = 0; ii < 8; ii++)
#pragma unroll
            for (int p = 0; p < 2; p++) {
                unsigned lo0, hi0, lo1, hi1;
                split2(lo0, hi0, acc[ii][2 * p]);
                split2(lo1, hi1, acc[ii][2 * p + 1]);
                unsigned t0 = prmt(lo0, hi0, 0xFBFBu);
                unsigned t1 = prmt(lo1, hi1, 0xFBFBu);
                msk[ii][p] |= prmt(t0, t1, 0x5410u);
            }
    }

    // ---- epilogue: sign byte==0 -> 1.0f ----
    // direct: A[i, j]
#pragma unroll
    for (int ii = 0; ii < 8; ii++)
#pragma unroll
        for (int p = 0; p < 2; p++) {
            unsigned m = msk[ii][p];
            float4 o;
            o.x = (m & 0x00000080u) ? 0.0f : 1.0f;
            o.y = (m & 0x00008000u) ? 0.0f : 1.0f;
            o.z = (m & 0x00800000u) ? 0.0f : 1.0f;
            o.w = (m & 0x80000000u) ? 0.0f : 1.0f;
            size_t off = (size_t)(i0 + ty * 8 + ii) * 4096 + j0 + p * 32 + tx * 4;
            *(float4*)&A[off] = o;
        }
    // transposed: A[j, i]; skip rows inside this tile's i-range (diag tiles)
#pragma unroll
    for (int p = 0; p < 2; p++)
#pragma unroll
        for (int c = 0; c < 4; c++) {
            int rowj = j0 + p * 32 + tx * 4 + c;
            if (rowj >= i0 && rowj < i0 + 64) continue;   // diag: direct covers
            unsigned bit = 0x80u << (8 * c);
            float4 o0, o1;
            o0.x = (msk[0][p] & bit) ? 0.0f : 1.0f;
            o0.y = (msk[1][p] & bit) ? 0.0f : 1.0f;
            o0.z = (msk[2][p] & bit) ? 0.0f : 1.0f;
            o0.w = (msk[3][p] & bit) ? 0.0f : 1.0f;
            o1.x = (msk[4][p] & bit) ? 0.0f : 1.0f;
            o1.y = (msk[5][p] & bit) ? 0.0f : 1.0f;
            o1.z = (msk[6][p] & bit) ? 0.0f : 1.0f;
            o1.w = (msk[7][p] & bit) ? 0.0f : 1.0f;
            size_t off = (size_t)rowj * 4096 + i0 + ty * 8;
            *(float4*)&A[off]     = o0;
            *(float4*)&A[off + 4] = o1;
        }
}

// ---------------------------------------------------------------------------
extern "C" void kernel_launch(void* const* d_in, const int* in_sizes, int n_in,
                              void* d_out, int out_size) {
    const float* x = (const float*)d_in[0];
    float* A = (float*)d_out;

    prep1_kernel<<<256, 256>>>(x);         // one block per (r,k) slice
    prep2_kernel<<<64, 256>>>();           // rows 16,17
    gram_kernel<<<2080, 64>>>(A);          // 64x64 triangle tiles
}

// round 8
// speedup vs baseline: 1.2857x; 1.0204x over previous
#include <cuda_runtime.h>

// ---------------------------------------------------------------------------
// GraphConstruction: A[i,j] = all_k( ||patch_i[:,k]-patch_j[:,k]||_2 <= 7 )
// score_k(i,j) = sum_{r<16} P[i,r,k]*P[j,r,k] + 1*c_j + c_i*1,  c = 12.25-sq/2
// A[i,j] = no k has score_k < 0 (OR of sign bits == 0).
// gram kernel: identical to R6 (pipe-floor bound, bit-stable rel_err).
// R7: prep kernels re-gridded for latency hiding (5.5+1.3 -> ~2.6 us).
// ---------------------------------------------------------------------------

#define NP 4096
#define RAUG 18

static __device__ float g_P[16 * RAUG * NP];   // [k][r][n], 4.5 MB

// ---------------- helpers ---------------------------------------------------
__device__ __forceinline__ unsigned long long bcast2(float x) {
    unsigned long long r;
    asm("mov.b64 %0, {%1, %1};" : "=l"(r) : "f"(x));
    return r;
}
__device__ __forceinline__ void ffma2(unsigned long long& d,
                                      unsigned long long a,
                                      unsigned long long b) {
    asm("fma.rn.f32x2 %0, %1, %2, %3;" : "=l"(d) : "l"(a), "l"(b), "l"(d));
}
__device__ __forceinline__ void split2(unsigned& lo, unsigned& hi,
                                       unsigned long long v) {
    asm("mov.b64 {%0, %1}, %2;" : "=r"(lo), "=r"(hi) : "l"(v));
}
__device__ __forceinline__ unsigned prmt(unsigned a, unsigned b, unsigned sel) {
    unsigned d;
    asm("prmt.b32 %0, %1, %2, %3;" : "=r"(d) : "r"(a), "r"(b), "r"(sel));
    return d;
}
__device__ __forceinline__ void cp_async16(void* smem, const void* gmem) {
    unsigned s = (unsigned)__cvta_generic_to_shared(smem);
    asm volatile("cp.async.cg.shared.global [%0], [%1], 16;" :: "r"(s), "l"(gmem));
}
#define CP_COMMIT() asm volatile("cp.async.commit_group;")
#define CP_WAIT0()  asm volatile("cp.async.wait_group 0;")

// ---------------- prep 1: gather x into g_P rows 0..15 ----------------------
// 1024 blocks: (r,k) slice x quarter-of-n. Thread stores one contiguous float4.
// n = q*1024 + t*4 + c4 -> warp reads 4 rows x 32B segments, writes 512B bursts.
__global__ void prep1_kernel(const float* __restrict__ x) {
    const int q  = blockIdx.x & 3;
    const int rk = blockIdx.x >> 2;
    const int k = rk & 15;
    const int r = rk >> 4;
    const int t = threadIdx.x;                 // 256 threads
    const int wbase = (16 * (r & 3) + k) << 4;
    const int hb    = (r >> 2) << 4;
    const int nbase = q * 1024 + t * 4;
    float v[4];
#pragma unroll
    for (int c4 = 0; c4 < 4; c4++) {
        int n = nbase + c4;
        int h = ((n & 15) << 6) + hb + (n >> 8);
        int w = wbase + ((n >> 4) & 15);
        v[c4] = x[h * 1024 + w];
    }
    *(float4*)&g_P[(k * RAUG + r) * NP + nbase] =
        make_float4(v[0], v[1], v[2], v[3]);
}

// ---------------- prep 2: augmentation rows 16,17 ---------------------------
// 2 n per thread (float2); per-n scalar fmaf chain r=0..15 (bit-identical sq).
__global__ void prep2_kernel() {
    int idx = blockIdx.x * blockDim.x + threadIdx.x;   // [0, 16*2048)
    int n2 = idx & 2047;
    int k = idx >> 11;
    float s0 = 0.0f, s1 = 0.0f;
#pragma unroll
    for (int r = 0; r < 16; r++) {
        float2 v = *(const float2*)&g_P[(k * RAUG + r) * NP + n2 * 2];
        s0 = fmaf(v.x, v.x, s0);
        s1 = fmaf(v.y, v.y, s1);
    }
    *(float2*)&g_P[(k * RAUG + 16) * NP + n2 * 2] = make_float2(1.0f, 1.0f);
    *(float2*)&g_P[(k * RAUG + 17) * NP + n2 * 2] =
        make_float2(12.25f - 0.5f * s0, 12.25f - 0.5f * s1);
}

// ---------------- main: tiled pair kernel (identical to R6) -----------------
// Tile 64 i x 64 j, 64 threads, 8x8 per thread (j packed as f32x2).
__global__ void __launch_bounds__(64, 8) gram_kernel(float* __restrict__ A) {
    const int bid = blockIdx.x;
    int jb = (int)((sqrtf(8.0f * (float)bid + 1.0f) - 1.0f) * 0.5f);
    while ((jb * (jb + 1)) / 2 > bid) jb--;
    while (((jb + 1) * (jb + 2)) / 2 <= bid) jb++;
    const int ib = bid - (jb * (jb + 1)) / 2;   // 0..jb
    const int i0 = ib * 64;
    const int j0 = jb * 64;

    __shared__ __align__(16) float sA[2][RAUG][64];
    __shared__ __align__(16) float sB[2][RAUG][64];

    const int tid = threadIdx.x;
    const int tx = tid & 7;              // j group: j = {tx*4..+3} U {32+tx*4..+3}
    const int ty = tid >> 3;             // i group 0..7

    auto issue = [&](int buf, int k) {
        for (int idx = tid; idx < 288; idx += 64) {      // sA: 18 x 16 float4
            int r = idx >> 4, c = idx & 15;
            cp_async16(&sA[buf][r][c * 4], &g_P[(k * RAUG + r) * NP + i0 + c * 4]);
        }
        for (int idx = tid; idx < 288; idx += 64) {      // sB: rows 16/17 swapped
            int r = idx >> 4, c = idx & 15;
            int rs = (r < 16) ? r : (33 - r);
            cp_async16(&sB[buf][r][c * 4], &g_P[(k * RAUG + rs) * NP + j0 + c * 4]);
        }
    };

    unsigned msk[8][2];
#pragma unroll
    for (int a = 0; a < 8; a++) { msk[a][0] = 0u; msk[a][1] = 0u; }

    issue(0, 0);
    CP_COMMIT();

#pragma unroll 1
    for (int k = 0; k < 16; k++) {
        const int buf = k & 1;
        CP_WAIT0();
        __syncthreads();          // buf staged AND everyone done with buf^1
        if (k < 15) {
            issue(buf ^ 1, k + 1);
            CP_COMMIT();
        }

        unsigned long long acc[8][4];
#pragma unroll
        for (int a = 0; a < 8; a++)
#pragma unroll
            for (int b = 0; b < 4; b++) acc[a][b] = 0ULL;

#pragma unroll
        for (int r = 0; r < RAUG; r++) {
            float4 a0 = *(const float4*)&sA[buf][r][ty * 8];
            float4 a1 = *(const float4*)&sA[buf][r][ty * 8 + 4];
            ulonglong2 b0 = *(const ulonglong2*)&sB[buf][r][tx * 4];
            ulonglong2 b1 = *(const ulonglong2*)&sB[buf][r][32 + tx * 4];
            unsigned long long bb[4] = {b0.x, b0.y, b1.x, b1.y};
            float av[8] = {a0.x, a0.y, a0.z, a0.w, a1.x, a1.y, a1.z, a1.w};
#pragma unroll
            for (int ii = 0; ii < 8; ii++) {
                unsigned long long aa = bcast2(av[ii]);
#pragma unroll
                for (int jj = 0; jj < 4; jj++) ffma2(acc[ii][jj], aa, bb[jj]);
            }
        }

        // fold sign bits: msk[ii][p] bytes = signs of j = p*32 + tx*4 + {0..3}
#pragma unroll
        for (int ii = 0; ii < 8; ii++)
#pragma unroll
            for (int p = 0; p < 2; p++) {
                unsigned lo0, hi0, lo1, hi1;
                split2(lo0, hi0, acc[ii][2 * p]);
                split2(lo1, hi1, acc[ii][2 * p + 1]);
                unsigned t0 = prmt(lo0, hi0, 0xFBFBu);
                unsigned t1 = prmt(lo1, hi1, 0xFBFBu);
                msk[ii][p] |= prmt(t0, t1, 0x5410u);
            }
    }

    // ---- epilogue: sign byte==0 -> 1.0f ----
    // direct: A[i, j]
#pragma unroll
    for (int ii = 0; ii < 8; ii++)
#pragma unroll
        for (int p = 0; p < 2; p++) {
            unsigned m = msk[ii][p];
            float4 o;
            o.x = (m & 0x00000080u) ? 0.0f : 1.0f;
            o.y = (m & 0x00008000u) ? 0.0f : 1.0f;
            o.z = (m & 0x00800000u) ? 0.0f : 1.0f;
            o.w = (m & 0x80000000u) ? 0.0f : 1.0f;
            size_t off = (size_t)(i0 + ty * 8 + ii) * 4096 + j0 + p * 32 + tx * 4;
            *(float4*)&A[off] = o;
        }
    // transposed: A[j, i]; skip rows inside this tile's i-range (diag tiles)
#pragma unroll
    for (int p = 0; p < 2; p++)
#pragma unroll
        for (int c = 0; c < 4; c++) {
            int rowj = j0 + p * 32 + tx * 4 + c;
            if (rowj >= i0 && rowj < i0 + 64) continue;   // diag: direct covers
            unsigned bit = 0x80u << (8 * c);
            float4 o0, o1;
            o0.x = (msk[0][p] & bit) ? 0.0f : 1.0f;
            o0.y = (msk[1][p] & bit) ? 0.0f : 1.0f;
            o0.z = (msk[2][p] & bit) ? 0.0f : 1.0f;
            o0.w = (msk[3][p] & bit) ? 0.0f : 1.0f;
            o1.x = (msk[4][p] & bit) ? 0.0f : 1.0f;
            o1.y = (msk[5][p] & bit) ? 0.0f : 1.0f;
            o1.z = (msk[6][p] & bit) ? 0.0f : 1.0f;
            o1.w = (msk[7][p] & bit) ? 0.0f : 1.0f;
            size_t off = (size_t)rowj * 4096 + i0 + ty * 8;
            *(float4*)&A[off]     = o0;
            *(float4*)&A[off + 4] = o1;
        }
}

// ---------------------------------------------------------------------------
extern "C" void kernel_launch(void* const* d_in, const int* in_sizes, int n_in,
                              void* d_out, int out_size) {
    const float* x = (const float*)d_in[0];
    float* A = (float*)d_out;

    prep1_kernel<<<1024, 256>>>(x);        // (r,k) slice x n-quarter
    prep2_kernel<<<128, 256>>>();          // rows 16,17 (2 n / thread)
    gram_kernel<<<2080, 64>>>(A);          // 64x64 triangle tiles
}